// round 15
// baseline (speedup 1.0000x reference)
#include <cuda_runtime.h>
#include <cuda_fp16.h>

#define NVOX 2097152u            // 128^3
#define PLANE 16384              // 128*128
#define CH 32                    // output z-planes per block

// Scratch, fp16, 218 MB: mind channel-planar [tn][c(12)][z][y][x] halves,
// mind_var at half-offset 48*NVOX: [tn][z][y][x].
__device__ __half g_ssd[(size_t)52 * NVOX];
__device__ float g_msum[2] = {0.f, 0.f};
__device__ float g_loss = 0.f;

__device__ __forceinline__ unsigned h2u(__half2 h) { return *reinterpret_cast<unsigned*>(&h); }
__device__ __forceinline__ __half2  u2h(unsigned u) { return *reinterpret_cast<__half2*>(&u); }

// emit plane zo for 2 voxels (half2 lanes = columns a,b). a+b partials in half2.
__device__ __forceinline__ void emit(int zo, const __half2* __restrict__ pa,
                                     const __half2* __restrict__ pb,
                                     __half* __restrict__ outC,
                                     __half* __restrict__ outM, float& mvsum)
{
    __half2 v[12];
    #pragma unroll
    for (int c = 0; c < 12; ++c) v[c] = __hadd2(pa[c], pb[c]);
    __half2 mn = v[0], sm = v[0];
    #pragma unroll
    for (int c = 1; c < 12; ++c) { mn = __hmin2(mn, v[c]); sm = __hadd2(sm, v[c]); }
    const __half2 k12 = __float2half2_rn(1.f / 12.f);
    __half2 mv = __hfma2(sm, k12, __hneg2(mn));
    __half* oz = outC + (size_t)zo * PLANE;
    #pragma unroll
    for (int c = 0; c < 12; ++c)
        *reinterpret_cast<__half2*>(oz + (size_t)c * NVOX) = __hsub2(v[c], mn);
    *reinterpret_cast<__half2*>(outM + (size_t)zo * PLANE) = mv;
    float2 f = __half22float2(mv);
    mvsum += f.x + f.y;
}

__global__ __launch_bounds__(256, 3)
void ssd_kernel(const float* __restrict__ pred, const float* __restrict__ targ)
{
    const int tx = threadIdx.x;           // 0..63, columns (2tx, 2tx+1)
    const int ty = threadIdx.y;           // 0..3
    const int y0 = blockIdx.x * 4;
    const int zc = blockIdx.y;
    const int tn = blockIdx.z;
    const int t  = tn >> 1;
    const int n  = tn & 1;

    const int z0 = zc * CH, z1 = z0 + CH;
    const int zlo = max(z0 - 1, 0);
    const int zhi = min(z1, 127);

    const float* img = (t == 0 ? pred : targ) + (size_t)n * NVOX;
    const unsigned vox0 = (unsigned)(y0 + ty) * 128u + (unsigned)(2 * tx);
    __half* outC = g_ssd + (size_t)tn * 12u * NVOX + vox0;
    __half* outM = g_ssd + (size_t)48 * NVOX + (size_t)tn * NVOX + vox0;

    __shared__ __half simg[6][10][128];          // 15 KB, fp16 image ring
    __shared__ uint4  ysbE4[2][4][64];           // even cols, ch 0..7
    __shared__ uint2  ysbE2[2][4][64];           // even cols, ch 8..11
    __shared__ uint4  ysbO4[2][4][64];           // odd  cols, ch 0..7
    __shared__ uint2  ysbO2[2][4][64];           // odd  cols, ch 8..11
    float* red = (float*)ysbE4;                  // reduction aliases ysb post-loop

    const int lin = ty * 64 + tx;

    // staging offsets: plane = 10 rows x 64 half2
    int sofs[3], gofs[3];
    #pragma unroll
    for (int k = 0; k < 3; ++k) {
        int j = lin + k * 256;
        int row = j >> 6, cp = j & 63;
        int gy = min(max(y0 - 3 + row, 0), 127);
        sofs[k] = j;
        gofs[k] = gy * 64 + cp;
    }
    const bool sv2 = lin < 128;   // k=2 valid only for first 128 threads (640 half2)

    // preload planes zlo-2 .. zlo+2
    for (int q = zlo - 2; q <= zlo + 2; ++q) {
        const int slot = (q + 12) % 6;
        const float2* src = (const float2*)(img + (size_t)min(max(q, 0), 127) * PLANE);
        __half2* S = (__half2*)&simg[slot][0][0];
        S[sofs[0]] = __float22half2_rn(src[gofs[0]]);
        S[sofs[1]] = __float22half2_rn(src[gofs[1]]);
        if (sv2) S[sofs[2]] = __float22half2_rn(src[gofs[2]]);
    }
    // prefetch plane zlo+3 (convert to half2 at load — fewer live regs)
    __half2 pf[3];
    {
        const float2* src = (const float2*)(img + (size_t)min(zlo + 3, 127) * PLANE);
        pf[0] = __float22half2_rn(src[gofs[0]]);
        pf[1] = __float22half2_rn(src[gofs[1]]);
        if (sv2) pf[2] = __float22half2_rn(src[gofs[2]]);
    }
    __syncthreads();

    const int gy0 = y0 + ty;
    const bool atL = (tx == 0), atR = (tx == 63);
    const int txm = max(tx - 1, 0), txp = min(tx + 1, 63);
    const int dxm = atL ? 0 : 1, dxp = atR ? 0 : 1;   // derive rxm/rxp from rA

    // hoist z-invariant sample offsets (half2 indices; per dy = -1,0,1)
    int rA[3], rmA[3], rpA[3];
    #pragma unroll
    for (int k = 0; k < 3; ++k) {
        int ly = min(max(gy0 + (k - 1), 0), 127);
        rA[k]  = (ly - y0 + 3) * 64 + tx;
        rmA[k] = (max(ly - 2, 0)   - y0 + 3) * 64 + tx;
        rpA[k] = (min(ly + 2, 127) - y0 + 3) * 64 + tx;
    }

    __half2 prev[12], pair[12];
    float mvsum = 0.f;

    for (int zp = zlo; zp <= zhi; ++zp) {
        const __half2* Pzm = (const __half2*)&simg[(zp + 4) % 6][0][0];  // z-2
        const __half2* Pzc = (const __half2*)&simg[ zp      % 6][0][0];  // z
        const __half2* Pzp = (const __half2*)&simg[(zp + 2) % 6][0][0];  // z+2

        __half2 ys[12];
        #pragma unroll
        for (int c = 0; c < 12; ++c) ys[c] = __float2half2_rn(0.f);

        #pragma unroll
        for (int k = 0; k < 3; ++k) {
            __half2 V0 = Pzm[rA[k]];          // z-2
            __half2 V1 = Pzc[rA[k] - dxm];    // x-2 pair
            __half2 V2 = Pzc[rmA[k]];         // y-2
            __half2 V3 = Pzc[rA[k] + dxp];    // x+2 pair
            __half2 V4 = Pzp[rA[k]];          // z+2
            __half2 V5 = Pzc[rpA[k]];         // y+2
            if (atL) V1 = __half2half2(__low2half(V1));    // x clamp at 0
            if (atR) V3 = __half2half2(__high2half(V3));   // x clamp at 127
            __half2 d;
            d = __hsub2(V1, V0); ys[0]  = __hfma2(d, d, ys[0]);
            d = __hsub2(V2, V0); ys[1]  = __hfma2(d, d, ys[1]);
            d = __hsub2(V2, V1); ys[2]  = __hfma2(d, d, ys[2]);
            d = __hsub2(V3, V0); ys[3]  = __hfma2(d, d, ys[3]);
            d = __hsub2(V3, V2); ys[4]  = __hfma2(d, d, ys[4]);
            d = __hsub2(V4, V1); ys[5]  = __hfma2(d, d, ys[5]);
            d = __hsub2(V4, V2); ys[6]  = __hfma2(d, d, ys[6]);
            d = __hsub2(V4, V3); ys[7]  = __hfma2(d, d, ys[7]);
            d = __hsub2(V5, V0); ys[8]  = __hfma2(d, d, ys[8]);
            d = __hsub2(V5, V1); ys[9]  = __hfma2(d, d, ys[9]);
            d = __hsub2(V5, V3); ys[10] = __hfma2(d, d, ys[10]);
            d = __hsub2(V5, V4); ys[11] = __hfma2(d, d, ys[11]);
        }

        // publish: deinterleave even/odd columns, channel-paired half2s
        const int buf = zp & 1;
        {
            __half2 e0 = __lows2half2 (ys[0], ys[1]),  e1 = __lows2half2 (ys[2], ys[3]);
            __half2 e2 = __lows2half2 (ys[4], ys[5]),  e3 = __lows2half2 (ys[6], ys[7]);
            __half2 e4 = __lows2half2 (ys[8], ys[9]),  e5 = __lows2half2 (ys[10], ys[11]);
            __half2 o0 = __highs2half2(ys[0], ys[1]),  o1 = __highs2half2(ys[2], ys[3]);
            __half2 o2 = __highs2half2(ys[4], ys[5]),  o3 = __highs2half2(ys[6], ys[7]);
            __half2 o4 = __highs2half2(ys[8], ys[9]),  o5 = __highs2half2(ys[10], ys[11]);
            ysbE4[buf][ty][tx] = make_uint4(h2u(e0), h2u(e1), h2u(e2), h2u(e3));
            ysbE2[buf][ty][tx] = make_uint2(h2u(e4), h2u(e5));
            ysbO4[buf][ty][tx] = make_uint4(h2u(o0), h2u(o1), h2u(o2), h2u(o3));
            ysbO2[buf][ty][tx] = make_uint2(h2u(o4), h2u(o5));
        }

        // stage plane zp+3; prefetch zp+4
        {
            __half2* S = (__half2*)&simg[(zp + 3) % 6][0][0];
            S[sofs[0]] = pf[0];
            S[sofs[1]] = pf[1];
            if (sv2) S[sofs[2]] = pf[2];
            const float2* src = (const float2*)(img + (size_t)min(zp + 4, 127) * PLANE);
            pf[0] = __float22half2_rn(src[gofs[0]]);
            pf[1] = __float22half2_rn(src[gofs[1]]);
            if (sv2) pf[2] = __float22half2_rn(src[gofs[2]]);
        }

        __syncthreads();

        // neighbor columns: left's odd col = my a-1; right's even col = my b+1
        uint4 L4 = ysbO4[buf][ty][txm]; uint2 L2 = ysbO2[buf][ty][txm];
        uint4 R4 = ysbE4[buf][ty][txp]; uint2 R2 = ysbE2[buf][ty][txp];
        __half2 Lp[6] = {u2h(L4.x), u2h(L4.y), u2h(L4.z), u2h(L4.w), u2h(L2.x), u2h(L2.y)};
        __half2 Rp[6] = {u2h(R4.x), u2h(R4.y), u2h(R4.z), u2h(R4.w), u2h(R2.x), u2h(R2.y)};

        __half2 s[12];
        #pragma unroll
        for (int p = 0; p < 6; ++p) {
            __half2 mixe = __lows2half2 (Lp[p], Rp[p]);   // (L_{2p},   R_{2p})
            __half2 mixo = __highs2half2(Lp[p], Rp[p]);   // (L_{2p+1}, R_{2p+1})
            if (atL) {
                mixe = __halves2half2(__low2half(ys[2*p]),   __high2half(mixe));
                mixo = __halves2half2(__low2half(ys[2*p+1]), __high2half(mixo));
            }
            if (atR) {
                mixe = __halves2half2(__low2half(mixe), __high2half(ys[2*p]));
                mixo = __halves2half2(__low2half(mixo), __high2half(ys[2*p+1]));
            }
            __half2 me = __hadd2(ys[2*p],   __lowhigh2highlow(ys[2*p]));
            __half2 mo = __hadd2(ys[2*p+1], __lowhigh2highlow(ys[2*p+1]));
            s[2*p]   = __hadd2(me, mixe);
            s[2*p+1] = __hadd2(mo, mixo);
        }

        // rolling z window
        if (zp == zlo) {
            #pragma unroll
            for (int c = 0; c < 12; ++c) { prev[c] = s[c]; pair[c] = __hadd2(s[c], s[c]); }
            // pair=2s only used when z0==0 (virtual plane -1 == plane 0)
        } else {
            const int zo = zp - 1;
            if (zo >= z0) emit(zo, pair, s, outC, outM, mvsum);
            #pragma unroll
            for (int c = 0; c < 12; ++c) { pair[c] = __hadd2(prev[c], s[c]); prev[c] = s[c]; }
        }
    }
    if (z1 == 128) emit(127, pair, prev, outC, outM, mvsum);

    // block-reduce mind_var partial sum (red aliases ysb — safe after loop)
    __syncthreads();
    red[lin] = mvsum;
    __syncthreads();
    for (int off = 128; off > 0; off >>= 1) {
        if (lin < off) red[lin] += red[lin + off];
        __syncthreads();
    }
    if (lin == 0) atomicAdd(&g_msum[t], red[0]);
}

__global__ __launch_bounds__(256)
void loss_kernel()
{
    // 8 voxels per thread; channel-planar half layout
    const unsigned i8 = blockIdx.x * 256u + threadIdx.x;   // 0 .. 2*NVOX/8-1
    const float mP = g_msum[0] * (1.f / 4194304.f);
    const float mT = g_msum[1] * (1.f / 4194304.f);

    const unsigned v8 = i8 * 8u;
    const unsigned nn = v8 >> 21;
    const unsigned s  = v8 & (NVOX - 1u);
    const unsigned q  = s >> 3;                   // uint4 index (8 halfs)

    const unsigned tnP = nn, tnT = 2u + nn;

    // mind_var for 8 voxels each
    uint4 mvPu = ((const uint4*)(g_ssd + (size_t)48 * NVOX + (size_t)tnP * NVOX))[q];
    uint4 mvTu = ((const uint4*)(g_ssd + (size_t)48 * NVOX + (size_t)tnT * NVOX))[q];
    const __half* mvPh = (const __half*)&mvPu;
    const __half* mvTh = (const __half*)&mvTu;

    __half2 nivP[4], nivT[4];
    #pragma unroll
    for (int j = 0; j < 4; ++j) {
        float a0 = fminf(fmaxf(__half2float(mvPh[2*j]),   0.001f * mP), 1000.f * mP);
        float a1 = fminf(fmaxf(__half2float(mvPh[2*j+1]), 0.001f * mP), 1000.f * mP);
        float b0 = fminf(fmaxf(__half2float(mvTh[2*j]),   0.001f * mT), 1000.f * mT);
        float b1 = fminf(fmaxf(__half2float(mvTh[2*j+1]), 0.001f * mT), 1000.f * mT);
        nivP[j] = __floats2half2_rn(-1.f / a0, -1.f / a1);
        nivT[j] = __floats2half2_rn(-1.f / b0, -1.f / b1);
    }

    float acc = 0.f;
    #pragma unroll
    for (int c = 0; c < 12; ++c) {
        uint4 mp = ((const uint4*)(g_ssd + (size_t)(tnP * 12u + c) * NVOX))[q];
        uint4 mt = ((const uint4*)(g_ssd + (size_t)(tnT * 12u + c) * NVOX))[q];
        const __half2* hp = (const __half2*)&mp;
        const __half2* ht = (const __half2*)&mt;
        #pragma unroll
        for (int j = 0; j < 4; ++j) {
            __half2 eP = h2exp(__hmul2(hp[j], nivP[j]));
            __half2 eT = h2exp(__hmul2(ht[j], nivT[j]));
            float2 d = __half22float2(__hsub2(eP, eT));
            acc += d.x * d.x + d.y * d.y;
        }
    }

    __shared__ float red[256];
    red[threadIdx.x] = acc;
    __syncthreads();
    for (int off = 128; off > 0; off >>= 1) {
        if (threadIdx.x < off) red[threadIdx.x] += red[threadIdx.x + off];
        __syncthreads();
    }
    if (threadIdx.x == 0) atomicAdd(&g_loss, red[0]);
}

__global__ void finish_kernel(float* __restrict__ out)
{
    out[0] = g_loss * (1.f / 50331648.f);
    g_loss = 0.f; g_msum[0] = 0.f; g_msum[1] = 0.f;
}

extern "C" void kernel_launch(void* const* d_in, const int* in_sizes, int n_in,
                              void* d_out, int out_size)
{
    const float* pred = (const float*)d_in[0];
    const float* targ = (const float*)d_in[1];

    ssd_kernel<<<dim3(32, 128 / CH, 4), dim3(64, 4)>>>(pred, targ);
    loss_kernel<<<2048, 256>>>();
    finish_kernel<<<1, 1>>>((float*)d_out);
}